// round 1
// baseline (speedup 1.0000x reference)
#include <cuda_runtime.h>

#define N0 500000
#define N1 100000
#define N2 10000
#define IN_CH 128
#define HID 16
#define OUT_CH 64

// Scratch (device globals; no allocation allowed)
__device__ float g_xp[(size_t)N0 * HID];    // projected x (x @ W1), 32 MB
__device__ float g_sum1[(size_t)N1 * HID];  // layer-1 segment sums, then h1 in place
__device__ float g_cnt1[N1];
__device__ float g_sum2[(size_t)N2 * HID];  // layer-2 segment sums
__device__ float g_cnt2[N2];

// ---------------------------------------------------------------------------
__global__ void k_zero() {
    int i = blockIdx.x * blockDim.x + threadIdx.x;
    if (i < N1 * HID) g_sum1[i] = 0.0f;
    if (i < N1)       g_cnt1[i] = 0.0f;
    if (i < N2 * HID) g_sum2[i] = 0.0f;
    if (i < N2)       g_cnt2[i] = 0.0f;
}

// xp[row] = x[row] @ W1   (128 -> 16), thread per row, W1 staged in smem
__global__ void k_project(const float* __restrict__ x, const float* __restrict__ W1) {
    __shared__ float w[IN_CH * HID];
    for (int i = threadIdx.x; i < IN_CH * HID; i += blockDim.x) w[i] = W1[i];
    __syncthreads();
    int row = blockIdx.x * blockDim.x + threadIdx.x;
    if (row >= N0) return;

    float acc[HID];
#pragma unroll
    for (int j = 0; j < HID; j++) acc[j] = 0.0f;

    const float4* xr = (const float4*)(x + (size_t)row * IN_CH);
#pragma unroll 4
    for (int k4 = 0; k4 < IN_CH / 4; k4++) {
        float4 v = xr[k4];
        int k = k4 * 4;
#pragma unroll
        for (int j = 0; j < HID; j++) {
            acc[j] += v.x * w[(k + 0) * HID + j];
            acc[j] += v.y * w[(k + 1) * HID + j];
            acc[j] += v.z * w[(k + 2) * HID + j];
            acc[j] += v.w * w[(k + 3) * HID + j];
        }
    }
    float4* o = (float4*)(g_xp + (size_t)row * HID);
#pragma unroll
    for (int q = 0; q < HID / 4; q++)
        o[q] = make_float4(acc[q * 4 + 0], acc[q * 4 + 1], acc[q * 4 + 2], acc[q * 4 + 3]);
}

// layer-1 scatter: thread per (edge, dim)
__global__ void k_scatter1(const int* __restrict__ src, const int* __restrict__ dst, int E) {
    long long tid = (long long)blockIdx.x * blockDim.x + threadIdx.x;
    if (tid >= (long long)E * HID) return;
    int e = (int)(tid >> 4);
    int j = (int)(tid & 15);
    int s = src[e];
    int d = dst[e];
    atomicAdd(&g_sum1[(size_t)d * HID + j], g_xp[(size_t)s * HID + j]);
    if (j == 0) atomicAdd(&g_cnt1[d], 1.0f);
}

// h1 = relu(sum1 / max(cnt1,1) + b1)  (in place into g_sum1)
__global__ void k_finish1(const float* __restrict__ b1) {
    int i = blockIdx.x * blockDim.x + threadIdx.x;
    if (i >= N1 * HID) return;
    int row = i >> 4;
    int j = i & 15;
    float c = fmaxf(g_cnt1[row], 1.0f);
    float v = g_sum1[i] / c + b1[j];
    g_sum1[i] = fmaxf(v, 0.0f);
}

// layer-2 scatter: thread per (edge, dim), feat = h1 (in g_sum1)
__global__ void k_scatter2(const int* __restrict__ src, const int* __restrict__ dst, int E) {
    long long tid = (long long)blockIdx.x * blockDim.x + threadIdx.x;
    if (tid >= (long long)E * HID) return;
    int e = (int)(tid >> 4);
    int j = (int)(tid & 15);
    int s = src[e];
    int d = dst[e];
    atomicAdd(&g_sum2[(size_t)d * HID + j], g_sum1[(size_t)s * HID + j]);
    if (j == 0) atomicAdd(&g_cnt2[d], 1.0f);
}

// out = log_softmax(mean2 @ W2 + b2), warp per row (64 cols -> 2 per lane)
__global__ void k_out(const float* __restrict__ W2, const float* __restrict__ b2,
                      float* __restrict__ out) {
    __shared__ float w[HID * OUT_CH];
    __shared__ float bb[OUT_CH];
    for (int i = threadIdx.x; i < HID * OUT_CH; i += blockDim.x) w[i] = W2[i];
    if (threadIdx.x < OUT_CH) bb[threadIdx.x] = b2[threadIdx.x];
    __syncthreads();

    int warp = threadIdx.x >> 5;
    int lane = threadIdx.x & 31;
    int row = blockIdx.x * (blockDim.x / 32) + warp;
    if (row >= N2) return;

    float inv = 1.0f / fmaxf(g_cnt2[row], 1.0f);
    float m[HID];
#pragma unroll
    for (int k = 0; k < HID; k++) m[k] = g_sum2[(size_t)row * HID + k] * inv;

    float o0 = bb[lane];
    float o1 = bb[lane + 32];
#pragma unroll
    for (int k = 0; k < HID; k++) {
        o0 += m[k] * w[k * OUT_CH + lane];
        o1 += m[k] * w[k * OUT_CH + lane + 32];
    }

    float mx = fmaxf(o0, o1);
#pragma unroll
    for (int off = 16; off; off >>= 1) mx = fmaxf(mx, __shfl_xor_sync(0xffffffffu, mx, off));
    float s = __expf(o0 - mx) + __expf(o1 - mx);
#pragma unroll
    for (int off = 16; off; off >>= 1) s += __shfl_xor_sync(0xffffffffu, s, off);
    float lse = mx + __logf(s);

    out[(size_t)row * OUT_CH + lane] = o0 - lse;
    out[(size_t)row * OUT_CH + lane + 32] = o1 - lse;
}

// ---------------------------------------------------------------------------
extern "C" void kernel_launch(void* const* d_in, const int* in_sizes, int n_in,
                              void* d_out, int out_size) {
    const float* x   = (const float*)d_in[0];
    const float* W1  = (const float*)d_in[1];
    const float* b1  = (const float*)d_in[2];
    const float* W2  = (const float*)d_in[3];
    const float* b2  = (const float*)d_in[4];
    const int* src1  = (const int*)d_in[5];
    const int* dst1  = (const int*)d_in[6];
    const int* src2  = (const int*)d_in[7];
    const int* dst2  = (const int*)d_in[8];
    float* out = (float*)d_out;

    int E1 = in_sizes[5];
    int E2 = in_sizes[7];

    k_zero<<<(N1 * HID + 255) / 256, 256>>>();
    k_project<<<(N0 + 255) / 256, 256>>>(x, W1);
    {
        long long total = (long long)E1 * HID;
        int blocks = (int)((total + 255) / 256);
        k_scatter1<<<blocks, 256>>>(src1, dst1, E1);
    }
    k_finish1<<<(N1 * HID + 255) / 256, 256>>>(b1);
    {
        long long total = (long long)E2 * HID;
        int blocks = (int)((total + 255) / 256);
        k_scatter2<<<blocks, 256>>>(src2, dst2, E2);
    }
    k_out<<<(N2 + 7) / 8, 256>>>(W2, b2, out);
}

// round 3
// speedup vs baseline: 1.2280x; 1.2280x over previous
#include <cuda_runtime.h>

#define N0 500000
#define N1 100000
#define N2 10000
#define IN_CH 128
#define HID 16
#define OUT_CH 64

// Scratch (device globals; no allocation allowed)
__device__ float g_xp[(size_t)N0 * HID];    // projected x (x @ W1), 32 MB
__device__ float g_sum1[(size_t)N1 * HID];  // layer-1 segment sums, then h1 in place
__device__ float g_cnt1[N1];
__device__ float g_sum2[(size_t)N2 * HID];  // layer-2 segment sums
__device__ float g_cnt2[N2];

__device__ __forceinline__ void red_add_v4(float* addr, float a, float b, float c, float d) {
    asm volatile("red.global.add.v4.f32 [%0], {%1,%2,%3,%4};"
                 :: "l"(addr), "f"(a), "f"(b), "f"(c), "f"(d) : "memory");
}

// ---------------------------------------------------------------------------
__global__ void k_zero() {
    int i = blockIdx.x * blockDim.x + threadIdx.x;
    if (i < N1 * HID) g_sum1[i] = 0.0f;
    if (i < N1)       g_cnt1[i] = 0.0f;
    if (i < N2 * HID) g_sum2[i] = 0.0f;
    if (i < N2)       g_cnt2[i] = 0.0f;
}

// xp[row] = x[row] @ W1   (128 -> 16), thread per row, W1 staged in smem
__global__ void k_project(const float* __restrict__ x, const float* __restrict__ W1) {
    __shared__ float w[IN_CH * HID];
    for (int i = threadIdx.x; i < IN_CH * HID; i += blockDim.x) w[i] = W1[i];
    __syncthreads();
    int row = blockIdx.x * blockDim.x + threadIdx.x;
    if (row >= N0) return;

    float acc[HID];
#pragma unroll
    for (int j = 0; j < HID; j++) acc[j] = 0.0f;

    const float4* xr = (const float4*)(x + (size_t)row * IN_CH);
#pragma unroll 8
    for (int k4 = 0; k4 < IN_CH / 4; k4++) {
        float4 v = xr[k4];
        int k = k4 * 4;
#pragma unroll
        for (int j = 0; j < HID; j++) {
            acc[j] += v.x * w[(k + 0) * HID + j];
            acc[j] += v.y * w[(k + 1) * HID + j];
            acc[j] += v.z * w[(k + 2) * HID + j];
            acc[j] += v.w * w[(k + 3) * HID + j];
        }
    }
    float4* o = (float4*)(g_xp + (size_t)row * HID);
#pragma unroll
    for (int q = 0; q < HID / 4; q++)
        o[q] = make_float4(acc[q * 4 + 0], acc[q * 4 + 1], acc[q * 4 + 2], acc[q * 4 + 3]);
}

// layer-1 scatter: ONE thread per edge; 4x LDG.128 gather + 4x red.v4.f32
__global__ void k_scatter1(const int* __restrict__ src, const int* __restrict__ dst, int E) {
    int e = blockIdx.x * blockDim.x + threadIdx.x;
    if (e >= E) return;
    int s = src[e];
    int d = dst[e];
    const float4* xr = (const float4*)(g_xp + (size_t)s * HID);
    float* sr = g_sum1 + (size_t)d * HID;
    float4 v0 = xr[0], v1 = xr[1], v2 = xr[2], v3 = xr[3];
    red_add_v4(sr + 0,  v0.x, v0.y, v0.z, v0.w);
    red_add_v4(sr + 4,  v1.x, v1.y, v1.z, v1.w);
    red_add_v4(sr + 8,  v2.x, v2.y, v2.z, v2.w);
    red_add_v4(sr + 12, v3.x, v3.y, v3.z, v3.w);
    atomicAdd(&g_cnt1[d], 1.0f);
}

// h1 = relu(sum1 / max(cnt1,1) + b1)  (in place into g_sum1)
__global__ void k_finish1(const float* __restrict__ b1) {
    int i = blockIdx.x * blockDim.x + threadIdx.x;
    if (i >= N1 * HID) return;
    int row = i >> 4;
    int j = i & 15;
    float inv = __frcp_rn(fmaxf(g_cnt1[row], 1.0f));
    float v = fmaf(g_sum1[i], inv, b1[j]);
    g_sum1[i] = fmaxf(v, 0.0f);
}

// layer-2 scatter: one thread per edge, feat = h1 (in g_sum1)
__global__ void k_scatter2(const int* __restrict__ src, const int* __restrict__ dst, int E) {
    int e = blockIdx.x * blockDim.x + threadIdx.x;
    if (e >= E) return;
    int s = src[e];
    int d = dst[e];
    const float4* xr = (const float4*)(g_sum1 + (size_t)s * HID);
    float* sr = g_sum2 + (size_t)d * HID;
    float4 v0 = xr[0], v1 = xr[1], v2 = xr[2], v3 = xr[3];
    red_add_v4(sr + 0,  v0.x, v0.y, v0.z, v0.w);
    red_add_v4(sr + 4,  v1.x, v1.y, v1.z, v1.w);
    red_add_v4(sr + 8,  v2.x, v2.y, v2.z, v2.w);
    red_add_v4(sr + 12, v3.x, v3.y, v3.z, v3.w);
    atomicAdd(&g_cnt2[d], 1.0f);
}

// out = log_softmax(mean2 @ W2 + b2), warp per row (64 cols -> 2 per lane)
// 256 threads/block = 8 warps = 8 rows per block.
__global__ void k_out(const float* __restrict__ W2, const float* __restrict__ b2,
                      float* __restrict__ out) {
    __shared__ float w[HID * OUT_CH];
    __shared__ float bb[OUT_CH];
    for (int i = threadIdx.x; i < HID * OUT_CH; i += blockDim.x) w[i] = W2[i];
    if (threadIdx.x < OUT_CH) bb[threadIdx.x] = b2[threadIdx.x];
    __syncthreads();

    int warp = threadIdx.x >> 5;
    int lane = threadIdx.x & 31;
    int row = blockIdx.x * (blockDim.x / 32) + warp;
    if (row >= N2) return;

    float inv = 1.0f / fmaxf(g_cnt2[row], 1.0f);
    float m[HID];
#pragma unroll
    for (int k = 0; k < HID; k++) m[k] = g_sum2[(size_t)row * HID + k] * inv;

    float o0 = bb[lane];
    float o1 = bb[lane + 32];
#pragma unroll
    for (int k = 0; k < HID; k++) {
        o0 += m[k] * w[k * OUT_CH + lane];
        o1 += m[k] * w[k * OUT_CH + lane + 32];
    }

    float mx = fmaxf(o0, o1);
#pragma unroll
    for (int off = 16; off; off >>= 1) mx = fmaxf(mx, __shfl_xor_sync(0xffffffffu, mx, off));
    float s = __expf(o0 - mx) + __expf(o1 - mx);
#pragma unroll
    for (int off = 16; off; off >>= 1) s += __shfl_xor_sync(0xffffffffu, s, off);
    float lse = mx + __logf(s);

    out[(size_t)row * OUT_CH + lane] = o0 - lse;
    out[(size_t)row * OUT_CH + lane + 32] = o1 - lse;
}

// ---------------------------------------------------------------------------
extern "C" void kernel_launch(void* const* d_in, const int* in_sizes, int n_in,
                              void* d_out, int out_size) {
    const float* x   = (const float*)d_in[0];
    const float* W1  = (const float*)d_in[1];
    const float* b1  = (const float*)d_in[2];
    const float* W2  = (const float*)d_in[3];
    const float* b2  = (const float*)d_in[4];
    const int* src1  = (const int*)d_in[5];
    const int* dst1  = (const int*)d_in[6];
    const int* src2  = (const int*)d_in[7];
    const int* dst2  = (const int*)d_in[8];
    float* out = (float*)d_out;

    int E1 = in_sizes[5];
    int E2 = in_sizes[7];

    k_zero<<<(N1 * HID + 255) / 256, 256>>>();
    k_project<<<(N0 + 255) / 256, 256>>>(x, W1);
    k_scatter1<<<(E1 + 255) / 256, 256>>>(src1, dst1, E1);
    k_finish1<<<(N1 * HID + 255) / 256, 256>>>(b1);
    k_scatter2<<<(E2 + 255) / 256, 256>>>(src2, dst2, E2);
    k_out<<<(N2 + 7) / 8, 256>>>(W2, b2, out);
}